// round 9
// baseline (speedup 1.0000x reference)
#include <cuda_runtime.h>
#include <cuda_bf16.h>
#include <math.h>
#include <cstdint>

#define NQ 32400
#define NT 32512          // 254*128 padded
#define CDIM 512
#define NCLS 19
#define KNN 9
#define SHORTL 16
#define LANEL 12
#define HWIN (270*480)
#define FULLHW (1080*1920)
#define NCHUNK 8          // K chunks of 64 bf16 (128B rows)
#define NTILE 254         // candidate tiles of 128
#define TOT (NTILE*NCHUNK)
#define QBLKS 127         // 256-row query blocks
#define NSTAGE 3
#define STAGEB 49152      // 32KB A + 16KB B

// ---------------- device scratch ----------------
__device__ float g_feats[(size_t)NT * CDIM];   // fp32 gathered feats
__device__ float g_fs[NT];                     // |f|^2 (pads -> 1e30)
__device__ int   g_cls[NQ];
__device__ float g_psq[NCLS];
// bf16 feats, TILE-major: [tile][chunk][128 rows x 128B], SW128 pre-swizzled per 8-row atom
__device__ __align__(1024) __nv_bfloat16 g_featsb[(size_t)NCHUNK * NT * 64];
__device__ int g_short[(size_t)NT * SHORTL];

// ---------------- helpers ----------------
__device__ __forceinline__ uint32_t smem_u32(const void* p) {
    uint32_t a;
    asm("{ .reg .u64 t; cvta.to.shared.u64 t, %1; cvt.u32.u64 %0, t; }" : "=r"(a) : "l"(p));
    return a;
}
__device__ __forceinline__ void mbar_init(uint32_t a, uint32_t n) {
    asm volatile("mbarrier.init.shared.b64 [%0], %1;" :: "r"(a), "r"(n) : "memory");
}
__device__ __forceinline__ void mbar_expect(uint32_t a, uint32_t bytes) {
    asm volatile("mbarrier.arrive.expect_tx.shared.b64 _, [%0], %1;" :: "r"(a), "r"(bytes) : "memory");
}
__device__ __forceinline__ void mbar_arrive(uint32_t a) {
    asm volatile("mbarrier.arrive.shared.b64 _, [%0];" :: "r"(a) : "memory");
}
__device__ __forceinline__ void mbar_wait_acq(uint32_t a, uint32_t ph) {
    asm volatile(
        "{\n\t.reg .pred P;\n"
        "W%=:\n\t"
        "mbarrier.try_wait.parity.acquire.cta.shared::cta.b64 P, [%0], %1, 0x989680;\n\t"
        "@P bra D%=;\n\t"
        "bra W%=;\n"
        "D%=:\n\t}"
        :: "r"(a), "r"(ph) : "memory");
}
__device__ __forceinline__ void bulk_g2s(uint32_t dst, const void* src, uint32_t bytes, uint32_t mbar) {
    asm volatile(
        "cp.async.bulk.shared::cluster.global.mbarrier::complete_tx::bytes [%0], [%1], %2, [%3];"
        :: "r"(dst), "l"(src), "r"(bytes), "r"(mbar) : "memory");
}
__device__ __forceinline__ void fence_async_shared() {
    asm volatile("fence.proxy.async.shared::cta;" ::: "memory");
}
__device__ __forceinline__ void ldsm4(uint32_t& r0, uint32_t& r1, uint32_t& r2, uint32_t& r3, uint32_t addr) {
    asm volatile("ldmatrix.sync.aligned.m8n8.x4.shared.b16 {%0,%1,%2,%3}, [%4];"
                 : "=r"(r0), "=r"(r1), "=r"(r2), "=r"(r3) : "r"(addr));
}
__device__ __forceinline__ void mma16816(float* c, uint32_t a0, uint32_t a1, uint32_t a2, uint32_t a3,
                                         uint32_t b0, uint32_t b1) {
    asm volatile("mma.sync.aligned.m16n8k16.row.col.f32.bf16.bf16.f32 "
                 "{%0,%1,%2,%3}, {%4,%5,%6,%7}, {%8,%9}, {%0,%1,%2,%3};"
                 : "+f"(c[0]), "+f"(c[1]), "+f"(c[2]), "+f"(c[3])
                 : "r"(a0), "r"(a1), "r"(a2), "r"(a3), "r"(b0), "r"(b1));
}
__device__ __forceinline__ uint32_t sw128(uint32_t x) { return x ^ ((x >> 3) & 0x70); }

template<int L>
__device__ __forceinline__ void insL(float (&d)[L], int (&ix)[L], float v, int j) {
    if (v < d[L - 1]) {
        d[L - 1] = v; ix[L - 1] = j;
        #pragma unroll
        for (int p = L - 1; p > 0; p--) {
            if (d[p] < d[p - 1]) {
                float tf = d[p]; d[p] = d[p - 1]; d[p - 1] = tf;
                int   ti = ix[p]; ix[p] = ix[p - 1]; ix[p - 1] = ti;
            }
        }
    }
}

// ---------------- kernel 0: zero output + prototype norms + fs pad ----------------
__global__ void zpsq_kernel(const float* __restrict__ protos, float4* out, int n4) {
    int i = blockIdx.x * blockDim.x + threadIdx.x;
    if (i < n4) out[i] = make_float4(0.f, 0.f, 0.f, 0.f);
    if (blockIdx.x == 0) {
        int tid = threadIdx.x;
        int w = tid >> 5, lane = tid & 31;
        for (int c = w; c < NCLS; c += 8) {
            float sacc = 0.f;
            for (int k = lane; k < CDIM; k += 32) {
                float v = protos[c * CDIM + k];
                sacc += v * v;
            }
            #pragma unroll
            for (int o = 16; o > 0; o >>= 1) sacc += __shfl_xor_sync(0xffffffffu, sacc, o);
            if (lane == 0) g_psq[c] = sacc;
        }
        if (tid < NT - NQ) g_fs[NQ + tid] = 1e30f;
    }
}

// ---------------- kernel 1: gather feats, |f|^2, argmax class ----------------
__global__ void prep_kernel(const float* __restrict__ feat,
                            const float* __restrict__ outp,
                            const int* __restrict__ sidx) {
    const int i = blockIdx.x;
    const int tid = threadIdx.x;
    const int s = sidx[i];

    float acc = 0.f;
    float* dst = g_feats + (size_t)i * CDIM;
    for (int c = tid; c < CDIM; c += 128) {
        float v = __ldg(feat + (size_t)c * HWIN + s);
        dst[c] = v;
        acc += v * v;
    }
    __shared__ float red[128];
    __shared__ float sval[NCLS];
    red[tid] = acc;
    if (tid < NCLS) sval[tid] = __ldg(outp + (size_t)tid * HWIN + s);
    __syncthreads();
    for (int st = 64; st > 0; st >>= 1) {
        if (tid < st) red[tid] += red[tid + st];
        __syncthreads();
    }
    if (tid == 0) {
        g_fs[i] = red[0];
        float best = sval[0]; int bc = 0;
        #pragma unroll
        for (int c = 1; c < NCLS; c++)
            if (sval[c] > best) { best = sval[c]; bc = c; }
        g_cls[i] = bc;
    }
}

// ---------------- kernel 2: fp32 -> bf16, tile-major, pre-swizzled (pads zeroed) ----
__global__ void convert_kernel() {
    int idx = blockIdx.x * blockDim.x + threadIdx.x;   // one 16B group of 8 bf16
    if (idx >= NT * 64) return;
    int r  = idx >> 6;
    int g8 = idx & 63;
    int k  = g8 * 8;
    int c  = k >> 6;
    int kin = k & 63;

    uint4 u = make_uint4(0u, 0u, 0u, 0u);
    if (r < NQ) {
        const float4* src = (const float4*)(g_feats + (size_t)r * CDIM + k);
        float4 v0 = src[0], v1 = src[1];
        __nv_bfloat162 p0 = __floats2bfloat162_rn(v0.x, v0.y);
        __nv_bfloat162 p1 = __floats2bfloat162_rn(v0.z, v0.w);
        __nv_bfloat162 p2 = __floats2bfloat162_rn(v1.x, v1.y);
        __nv_bfloat162 p3 = __floats2bfloat162_rn(v1.z, v1.w);
        u.x = *(uint32_t*)&p0; u.y = *(uint32_t*)&p1;
        u.z = *(uint32_t*)&p2; u.w = *(uint32_t*)&p3;
    }
    // tile-major: [tile][chunk][16 atoms x 1024B]
    size_t base = ((size_t)(r >> 7) * NCHUNK + c) * 16384 + (size_t)((r >> 3) & 15) * 1024;
    uint32_t inner = (uint32_t)((r & 7) * 128 + kin * 2);
    *(uint4*)((char*)g_featsb + base + sw128(inner)) = u;
}

// ---------------- kernel 3: HMMA GEMM + fused top-K (warp-level mbarrier pipeline) ----
#define SM_STG 1024
#define SM_TOTAL (SM_STG + NSTAGE * STAGEB)   // 148480

__global__ __launch_bounds__(512, 1) void dist_select_kernel() {
    extern __shared__ char smem[];
    const uint32_t sb = smem_u32(smem);
    const uint32_t MB_FULL = sb + 0;       // 3 x 8B
    const uint32_t MB_CONS = sb + 32;      // 3 x 8B

    const int tid = threadIdx.x;
    const int w = tid >> 5, l = tid & 31;
    const int qg = l >> 2, t4 = l & 3;
    const int wr = w >> 1, wc = w & 1;     // 8x2 warp grid: 32 rows x 64 cols per warp
    const int blk = blockIdx.x;
    const int row0 = blk * 256;
    const unsigned FULL = 0xffffffffu;

    if (tid == 0) {
        #pragma unroll
        for (int s = 0; s < NSTAGE; s++) {
            mbar_init(MB_FULL + 8 * s, 1);
            mbar_init(MB_CONS + 8 * s, 16);   // one arrive per warp
        }
        fence_async_shared();
    }
    __syncthreads();

    // prologue: stages 0,1 (A chunk pair + B chunk each)
    if (tid == 0) {
        #pragma unroll
        for (int it0 = 0; it0 < 2; it0++) {
            uint32_t dst = sb + SM_STG + (uint32_t)it0 * STAGEB;
            mbar_expect(MB_FULL + 8 * it0, STAGEB);
            bulk_g2s(dst,         (const char*)g_featsb + ((size_t)(2 * blk)     * NCHUNK + it0) * 16384, 16384, MB_FULL + 8 * it0);
            bulk_g2s(dst + 16384, (const char*)g_featsb + ((size_t)(2 * blk + 1) * NCHUNK + it0) * 16384, 16384, MB_FULL + 8 * it0);
            bulk_g2s(dst + 32768, (const char*)g_featsb + (size_t)it0 * 16384, 16384, MB_FULL + 8 * it0);
        }
    }

    // ---- per-lane ldmatrix addressing ----
    const int rowlA = l & 15;
    const int halfA = (l >> 4) & 1;
    const uint32_t maskA = (uint32_t)(rowlA & 7) << 4;
    const uint32_t aRowBase = (uint32_t)(wr * 32 + rowlA) * 128;
    const int rowlB = (l & 7) + ((l >> 4) << 3);
    const int halfB = (l >> 3) & 1;
    const uint32_t maskB = (uint32_t)(rowlB & 7) << 4;
    const uint32_t bRowBase = 32768 + (uint32_t)(wc * 64 + rowlB) * 128;

    // after transpose, this lane owns query row:
    const int rown = wr * 32 + qg + 8 * t4;

    float acc[2][8][4];
    #pragma unroll
    for (int m = 0; m < 2; m++)
        #pragma unroll
        for (int n = 0; n < 8; n++)
            #pragma unroll
            for (int c = 0; c < 4; c++) acc[m][n][c] = 0.f;

    float ld12[LANEL]; int li12[LANEL];
    #pragma unroll
    for (int k = 0; k < LANEL; k++) { ld12[k] = 3.0e38f; li12[k] = 0; }

    for (int it = 0; it < TOT; it++) {
        const int kc = it & 7;
        const int tile = it >> 3;

        // producer: issue stage it+2 once its slot has been consumed by all warps
        if (tid == 0) {
            int il = it + 2;
            if (il < TOT) {
                int slot = il % NSTAGE;
                if (il >= NSTAGE)
                    mbar_wait_acq(MB_CONS + 8 * slot, (uint32_t)(((il - NSTAGE) / NSTAGE) & 1));
                int t2 = il >> 3, k2 = il & 7;
                uint32_t dst = sb + SM_STG + (uint32_t)slot * STAGEB;
                mbar_expect(MB_FULL + 8 * slot, STAGEB);
                bulk_g2s(dst,         (const char*)g_featsb + ((size_t)(2 * blk)     * NCHUNK + k2) * 16384, 16384, MB_FULL + 8 * slot);
                bulk_g2s(dst + 16384, (const char*)g_featsb + ((size_t)(2 * blk + 1) * NCHUNK + k2) * 16384, 16384, MB_FULL + 8 * slot);
                bulk_g2s(dst + 32768, (const char*)g_featsb + ((size_t)t2 * NCHUNK + k2) * 16384, 16384, MB_FULL + 8 * slot);
            }
        }

        // consumer: wait stage it full
        mbar_wait_acq(MB_FULL + 8 * (it % NSTAGE), (uint32_t)((it / NSTAGE) & 1));

        const uint32_t stg = sb + SM_STG + (uint32_t)(it % NSTAGE) * STAGEB;
        const uint32_t abase = stg + aRowBase;
        const uint32_t bbase = stg + bRowBase;

        #pragma unroll
        for (int ks = 0; ks < 4; ks++) {
            uint32_t acol = ((uint32_t)(ks * 32 + halfA * 16)) ^ maskA;
            uint32_t bcol = ((uint32_t)(ks * 32 + halfB * 16)) ^ maskB;
            uint32_t a00, a01, a02, a03, a10, a11, a12, a13;
            ldsm4(a00, a01, a02, a03, abase + acol);
            ldsm4(a10, a11, a12, a13, abase + 2048 + acol);
            #pragma unroll
            for (int p = 0; p < 4; p++) {
                uint32_t b0, b1, b2, b3;
                ldsm4(b0, b1, b2, b3, bbase + (uint32_t)p * 2048 + bcol);
                mma16816(acc[0][2 * p],     a00, a01, a02, a03, b0, b1);
                mma16816(acc[0][2 * p + 1], a00, a01, a02, a03, b2, b3);
                mma16816(acc[1][2 * p],     a10, a11, a12, a13, b0, b1);
                mma16816(acc[1][2 * p + 1], a10, a11, a12, a13, b2, b3);
            }
        }

        // this warp is done reading stage it's smem
        __syncwarp();
        if (l == 0) mbar_arrive(MB_CONS + 8 * (it % NSTAGE));

        if (kc == 7) {
            // quad transpose: lane t4 gets full row (its 64 warp cols), then select
            const int jb = tile * 128 + wc * 64;
            #pragma unroll
            for (int n8 = 0; n8 < 8; n8++) {
                const float4 fjA = __ldg((const float4*)(g_fs + jb + n8 * 8));
                const float4 fjB = __ldg((const float4*)(g_fs + jb + n8 * 8 + 4));
                #pragma unroll
                for (int cb = 0; cb < 2; cb++) {
                    float e0 = acc[0][n8][cb],     e1 = acc[0][n8][2 + cb];
                    float e2 = acc[1][n8][cb],     e3 = acc[1][n8][2 + cb];
                    // round 1 (xor lane bit0 <-> slot bit0)
                    float s0 = __shfl_xor_sync(FULL, e1, 1);
                    float s1 = __shfl_xor_sync(FULL, e0, 1);
                    float s2 = __shfl_xor_sync(FULL, e3, 1);
                    float s3 = __shfl_xor_sync(FULL, e2, 1);
                    bool lo = ((t4 & 1) == 0);
                    float y0 = lo ? e0 : s0;
                    float y1 = lo ? s1 : e1;
                    float y2 = lo ? e2 : s2;
                    float y3 = lo ? s3 : e3;
                    // round 2 (xor lane bit1 <-> slot bit1)
                    float u0 = __shfl_xor_sync(FULL, y2, 2);
                    float u1 = __shfl_xor_sync(FULL, y3, 2);
                    float u2 = __shfl_xor_sync(FULL, y0, 2);
                    float u3 = __shfl_xor_sync(FULL, y1, 2);
                    bool hi = ((t4 & 2) == 0);
                    float x0 = hi ? y0 : u0;
                    float x1 = hi ? y1 : u1;
                    float x2 = hi ? u2 : y2;
                    float x3 = hi ? u3 : y3;
                    // x[s] = dot for col n8*8 + 2*s + cb; select on score = fj - 2*dot
                    float fj0 = cb ? fjA.y : fjA.x;
                    float fj1 = cb ? fjA.w : fjA.z;
                    float fj2 = cb ? fjB.y : fjB.x;
                    float fj3 = cb ? fjB.w : fjB.z;
                    int c0 = n8 * 8 + cb;
                    insL<LANEL>(ld12, li12, fmaf(-2.f, x0, fj0), jb + c0);
                    insL<LANEL>(ld12, li12, fmaf(-2.f, x1, fj1), jb + c0 + 2);
                    insL<LANEL>(ld12, li12, fmaf(-2.f, x2, fj2), jb + c0 + 4);
                    insL<LANEL>(ld12, li12, fmaf(-2.f, x3, fj3), jb + c0 + 6);
                }
            }
            #pragma unroll
            for (int m = 0; m < 2; m++)
                #pragma unroll
                for (int n = 0; n < 8; n++)
                    #pragma unroll
                    for (int c = 0; c < 4; c++) acc[m][n][c] = 0.f;
        }
    }

    // ---- final merge: 2 half-lists x 12 per row -> top-16 ----
    __syncthreads();
    float* dm = (float*)(smem + SM_STG);                       // 256*24*4 = 24576
    int*   im = (int*)(smem + SM_STG + 256 * 24 * 4);          // +24576
    #pragma unroll
    for (int k = 0; k < LANEL; k++) {
        dm[rown * 24 + wc * LANEL + k] = ld12[k];
        im[rown * 24 + wc * LANEL + k] = li12[k];
    }
    __syncthreads();
    if (tid < 256) {
        int row = row0 + tid;
        if (row < NQ) {
            float bd[SHORTL]; int bi[SHORTL];
            #pragma unroll
            for (int k = 0; k < SHORTL; k++) { bd[k] = 3.0e38f; bi[k] = 0; }
            #pragma unroll
            for (int e = 0; e < 24; e++)
                insL<SHORTL>(bd, bi, dm[tid * 24 + e], im[tid * 24 + e]);
            #pragma unroll
            for (int k = 0; k < SHORTL; k++) g_short[(size_t)row * SHORTL + k] = bi[k];
        }
    }
}

// ---------------- kernel 4: exact fp32 re-rank + entropy + proto rank + scatter ----
__global__ __launch_bounds__(256) void rerank_kernel(const float* __restrict__ protos,
                                                     const int* __restrict__ sidx,
                                                     float* __restrict__ out) {
    const int q = blockIdx.x * 8 + (threadIdx.x >> 5);
    if (q >= NQ) return;
    const int lane = threadIdx.x & 31;
    const unsigned FULL = 0xffffffffu;

    float qv[16];
    const float* fr = g_feats + (size_t)q * CDIM;
    #pragma unroll
    for (int i = 0; i < 16; i++) qv[i] = fr[i * 32 + lane];
    const float fq = g_fs[q];

    int myidx = (lane < SHORTL) ? g_short[(size_t)q * SHORTL + lane] : 0x7fffffff;
    float myd = 1e38f;

    #pragma unroll 1
    for (int c = 0; c < SHORTL; c++) {
        int cj = __shfl_sync(FULL, myidx, c);
        const float* cr = g_feats + (size_t)cj * CDIM;
        float acc = 0.f;
        #pragma unroll
        for (int i = 0; i < 16; i++) acc += qv[i] * __ldg(&cr[i * 32 + lane]);
        #pragma unroll
        for (int o = 16; o > 0; o >>= 1) acc += __shfl_xor_sync(FULL, acc, o);
        float d = fmaxf(fq + __ldg(&g_fs[cj]) - 2.f * acc, 1e-12f);
        if (lane == c) myd = d;
    }

    int rank = 0;
    #pragma unroll
    for (int o = 0; o < SHORTL; o++) {
        float od = __shfl_sync(FULL, myd, o);
        int   oi = __shfl_sync(FULL, myidx, o);
        if (o != lane && (od < myd || (od == myd && oi < myidx))) rank++;
    }
    int nbcls = (lane < SHORTL && rank < KNN) ? g_cls[myidx] : -1;

    float ent = 0.f;
    #pragma unroll
    for (int c = 0; c < NCLS; c++) {
        int cnt = __popc(__ballot_sync(FULL, nbcls == c));
        if (cnt > 0) {
            float p = (float)cnt * (1.f / 9.f);
            ent += -p * logf(p + 1e-6f);
        }
    }
    ent *= (1.f / logf(19.f));

    float pd = 1e38f;
    #pragma unroll 1
    for (int c = 0; c < NCLS; c++) {
        float acc = 0.f;
        #pragma unroll
        for (int i = 0; i < 16; i++) acc += qv[i] * __ldg(&protos[c * CDIM + i * 32 + lane]);
        #pragma unroll
        for (int o = 16; o > 0; o >>= 1) acc += __shfl_xor_sync(FULL, acc, o);
        if (lane == c) pd = fmaxf(fq + g_psq[c] - 2.f * acc, 1e-12f);
    }
    int myc = g_cls[q];
    float refd = __shfl_sync(FULL, pd, myc);
    unsigned m = __ballot_sync(FULL, (lane < NCLS) && (pd < refd || (pd == refd && lane < myc)));
    int prank = __popc(m);

    if (lane == 0) {
        int s = sidx[q];
        out[s] = ent;
        out[FULLHW + s] = (float)prank * (1.f / 18.f);
    }
}

// ---------------- launch ----------------
extern "C" void kernel_launch(void* const* d_in, const int* in_sizes, int n_in,
                              void* d_out, int out_size) {
    const float* feat   = nullptr;
    const float* outp   = nullptr;
    const float* protos = nullptr;
    const int*   sidx   = nullptr;
    for (int i = 0; i < n_in; i++) {
        switch (in_sizes[i]) {
            case 66355200: feat   = (const float*)d_in[i]; break;
            case 2462400:  outp   = (const float*)d_in[i]; break;
            case 9728:     protos = (const float*)d_in[i]; break;
            case 32400:    sidx   = (const int*)d_in[i];   break;
        }
    }
    float* out = (float*)d_out;

    static bool attr_done = false;
    if (!attr_done) {
        cudaFuncSetAttribute(dist_select_kernel,
                             cudaFuncAttributeMaxDynamicSharedMemorySize, SM_TOTAL);
        attr_done = true;
    }

    int n4 = out_size / 4;
    zpsq_kernel<<<(n4 + 255) / 256, 256>>>(protos, (float4*)out, n4);
    prep_kernel<<<NQ, 128>>>(feat, outp, sidx);
    convert_kernel<<<(NT * 64 + 255) / 256, 256>>>();
    dist_select_kernel<<<QBLKS, 512, SM_TOTAL>>>();
    rerank_kernel<<<(NQ + 7) / 8, 256>>>(protos, sidx, out);
}